// round 7
// baseline (speedup 1.0000x reference)
#include <cuda_runtime.h>
#include <math.h>

#define HH 512
#define WW 512
#define CHW 128
#define FHW 256
#define CF 256
#define NCc 3
#define NPTS 2048
#define NUM_OVER 6144
#define CHUNK 6                              // NUM_OVER / 1024
#define STEP1 1536
#define STEP2 512
#define BB 2
#define FEAT_DIM 259
#define FEAT_PAD 260
#define NCB1 65                              // 260/4
#define NROWS (BB*NPTS)                      // 4096
#define FINE_FLAT (BB*NPTS*CF)               // 1048576
#define OUT_OFF (BB*NCc*NPTS)                // 12288
#define MASK_SIZE (BB*HH*WW)
#define RPB 16
#define NPAIR (RPB/2)                        // 8
#define NWORDS (HH*WW/32)                    // 8192 (32KB)
#define W1P_ELEMS (NCB1*256*4)
#define W2P_ELEMS (NCB1*128*4)
#define PREP_SEL_BLOCKS 2
#define PREP_REPACK_BLOCKS 98
#define P_MAX 18                             // fine points touched per MLP block
#define SMLP_THREADS 512

// ---------------- device scratch ----------------
__device__ int   g_pts[BB*NPTS];
__device__ float g_cflat[BB*NPTS*NCc];       // coarse logits at sorted points
__device__ float g_w1p[W1P_ELEMS];           // [cb][o][q]
__device__ float g_w2p[W2P_ELEMS];

// ---------------- f32x2 helpers (FFMA2 path, bit-identical lanewise fma) --
__device__ __forceinline__ unsigned long long pk2(float lo, float hi) {
    unsigned long long r;
    asm("mov.b64 %0, {%1,%2};" : "=l"(r) : "f"(lo), "f"(hi));
    return r;
}
__device__ __forceinline__ void upk2(unsigned long long v, float& lo, float& hi) {
    asm("mov.b64 {%0,%1}, %2;" : "=f"(lo), "=f"(hi) : "l"(v));
}
__device__ __forceinline__ void fma2(unsigned long long& d, unsigned long long a,
                                     unsigned long long b) {
    asm("fma.rn.f32x2 %0, %1, %2, %0;" : "+l"(d) : "l"(a), "l"(b));
}

// =========================================================================
// k_prep: blocks 0..1 -> per-batch selection (radix threshold, all-parallel)
//                        + ordered emit + mask + coarse-logit gather
//         blocks 2..  -> weight repack
// =========================================================================
__global__ __launch_bounds__(1024) void k_prep(const float* __restrict__ coarse,
                                               const int* __restrict__ rnd,
                                               const float* __restrict__ w1,
                                               const float* __restrict__ w2,
                                               float* __restrict__ mask_out) {
    extern __shared__ unsigned int dyn[];    // 32KB: okey[6144] -> bitmap[8192]
    __shared__ int hist[256];
    __shared__ int sfxsum[257];
    __shared__ int warp_tot[32];
    __shared__ unsigned int s_prefix;
    __shared__ int s_need;

    if (blockIdx.x >= PREP_SEL_BLOCKS) {
        int t = (blockIdx.x - PREP_SEL_BLOCKS) * 1024 + threadIdx.x;
        if (t < W1P_ELEMS) {
            int cb = t >> 10, rest = t & 1023;
            int o = rest >> 2, q = rest & 3, c = cb * 4 + q;
            g_w1p[t] = (c < FEAT_DIM) ? w1[o*FEAT_DIM + c] : 0.f;
        } else {
            int t2 = t - W1P_ELEMS;
            if (t2 < W2P_ELEMS) {
                int cb = t2 >> 9, rest = t2 & 511;
                int o = rest >> 2, q = rest & 3, c = cb * 4 + q;
                g_w2p[t2] = (c < FEAT_DIM) ? w2[o*FEAT_DIM + c] : 0.f;
            }
        }
        return;
    }

    int b = blockIdx.x;
    int tid = threadIdx.x;
    int lane = tid & 31, wrp = tid >> 5;

    // ---- 1. uncertainty -> monotone okey (thread owns j = tid*6+jj) ----
    for (int jj = 0; jj < CHUNK; jj++) {
        int j = tid * CHUNK + jj;
        int idx = rnd[j];
        int h = idx / WW, w = idx % WW;
        float yc = (float)h * 0.25f - 0.375f;
        float xc = (float)w * 0.25f - 0.375f;
        int y0 = (int)floorf(yc); float fy = yc - (float)y0;
        int x0 = (int)floorf(xc); float fx = xc - (float)x0;
        int y0c = min(max(y0,   0), CHW-1), y1c = min(max(y0+1, 0), CHW-1);
        int x0c = min(max(x0,   0), CHW-1), x1c = min(max(x0+1, 0), CHW-1);
        float p[3];
        const float* base = coarse + (size_t)b * NCc * CHW * CHW;
#pragma unroll
        for (int c = 0; c < 3; c++) {
            const float* pc = base + c * CHW * CHW;
            float v00 = pc[y0c*CHW + x0c], v01 = pc[y0c*CHW + x1c];
            float v10 = pc[y1c*CHW + x0c], v11 = pc[y1c*CHW + x1c];
            float top = v00 * (1.f - fx) + v01 * fx;
            float bot = v10 * (1.f - fx) + v11 * fx;
            p[c] = top * (1.f - fy) + bot * fy;
        }
        float m  = fmaxf(p[0], fmaxf(p[1], p[2]));
        float e0 = expf(p[0]-m), e1 = expf(p[1]-m), e2 = expf(p[2]-m);
        float s  = e0 + e1 + e2;
        float q0 = e0/s, q1 = e1/s, q2 = e2/s;
        float mx  = fmaxf(q0, fmaxf(q1, q2));
        float mn  = fminf(q0, fminf(q1, q2));
        float mid = q0 + q1 + q2 - mx - mn;
        float u = 1.0f - (mx - mid);
        unsigned int bits = __float_as_uint(u);
        dyn[j] = bits ^ ((bits >> 31) ? 0xFFFFFFFFu : 0x80000000u);
    }
    if (tid == 0) { s_prefix = 0u; s_need = STEP1; }
    __syncthreads();

    // ---- 2. radix threshold, parallel suffix scan per level ----
    for (int lvl = 0; lvl < 4; lvl++) {
        int shift = 24 - 8*lvl;
        unsigned int hi_mask = lvl ? (0xFFFFFFFFu << (shift + 8)) : 0u;
        unsigned int pref = s_prefix;
        int need = s_need;
        if (tid < 256) hist[tid] = 0;
        __syncthreads();
#pragma unroll
        for (int jj = 0; jj < CHUNK; jj++) {
            unsigned int ok = dyn[tid*CHUNK + jj];
            if ((ok & hi_mask) == pref) atomicAdd(&hist[(ok >> shift) & 255], 1);
        }
        __syncthreads();
        int x = (tid < 256) ? hist[255 - tid] : 0;
#pragma unroll
        for (int o = 1; o < 32; o <<= 1) {
            int y = __shfl_up_sync(0xFFFFFFFFu, x, o);
            if (lane >= o) x += y;
        }
        if (tid < 256 && lane == 31) warp_tot[wrp] = x;
        __syncthreads();
        if (tid < 256) {
            int basew = 0;
            for (int wq = 0; wq < wrp; wq++) basew += warp_tot[wq];
            sfxsum[255 - tid] = x + basew;
        }
        __syncthreads();
        if (tid < 256) {
            int S  = sfxsum[tid];
            int S1 = (tid == 255) ? 0 : sfxsum[tid + 1];
            if (S >= need && S1 < need) {
                s_prefix = pref | ((unsigned int)tid << shift);
                s_need = need - S1;
            }
        }
        __syncthreads();
    }
    unsigned int T = s_prefix;
    int need = s_need;

    // ---- 3. tie ranks via block scan (index order == chunk order) ----
    unsigned int okv[CHUNK];
    int localeq = 0;
#pragma unroll
    for (int jj = 0; jj < CHUNK; jj++) {
        okv[jj] = dyn[tid*CHUNK + jj];
        localeq += (okv[jj] == T);
    }
    {
        int x = localeq;
#pragma unroll
        for (int o = 1; o < 32; o <<= 1) {
            int y = __shfl_up_sync(0xFFFFFFFFu, x, o);
            if (lane >= o) x += y;
        }
        if (lane == 31) warp_tot[wrp] = x;
        __syncthreads();
        int basew = 0;
        for (int wq = 0; wq < wrp; wq++) basew += warp_tot[wq];
        int rank = basew + x - localeq;
        unsigned int selmask = 0;
#pragma unroll
        for (int jj = 0; jj < CHUNK; jj++) {
            bool sel = okv[jj] > T;
            if (okv[jj] == T) { sel = (rank < need); rank++; }
            if (sel) selmask |= 1u << jj;
        }
        __syncthreads();
        // ---- 4. bitmap of linear indices (reuse dyn) ----
        for (int w = tid; w < NWORDS; w += 1024) dyn[w] = 0u;
        __syncthreads();
#pragma unroll
        for (int jj = 0; jj < CHUNK; jj++)
            if ((selmask >> jj) & 1u) {
                int lin = rnd[tid*CHUNK + jj];
                atomicOr(&dyn[lin >> 5], 1u << (lin & 31));
            }
    }
    for (int i = tid; i < STEP2; i += 1024) {
        int lin = rnd[HH*WW - STEP2 + i];
        atomicOr(&dyn[lin >> 5], 1u << (lin & 31));
    }
    __syncthreads();

    // ---- 5. popcount scan + ordered emit ----
    {
        int w0 = tid * 8;
        unsigned int words[8];
        int cnt = 0;
#pragma unroll
        for (int q = 0; q < 8; q++) { words[q] = dyn[w0 + q]; cnt += __popc(words[q]); }
        int incl = cnt;
#pragma unroll
        for (int o = 1; o < 32; o <<= 1) {
            int v = __shfl_up_sync(0xFFFFFFFFu, incl, o);
            if (lane >= o) incl += v;
        }
        if (lane == 31) warp_tot[wrp] = incl;
        __syncthreads();
        int basew = 0;
        for (int wq = 0; wq < wrp; wq++) basew += warp_tot[wq];
        int offset = basew + incl - cnt;
#pragma unroll
        for (int q = 0; q < 8; q++) {
            unsigned int m = words[q];
            int linbase = (w0 + q) * 32;
            while (m) {
                int bpos = __ffs(m) - 1; m &= m - 1;
                int lin = linbase + bpos;
                g_pts[b*NPTS + offset] = lin;
                mask_out[b*HH*WW + lin] = 1.0f;
                offset++;
            }
        }
    }
    __syncthreads();

    // ---- 6. coarse logits at the sorted points ----
    for (int t = tid; t < NPTS; t += 1024) {
        int lin = g_pts[b*NPTS + t];
        int h = lin >> 9, w = lin & 511;
        float yc = (float)h * 0.25f - 0.375f;
        float xc = (float)w * 0.25f - 0.375f;
        int cy = (int)floorf(yc); float cfy = yc - (float)cy;
        int cx = (int)floorf(xc); float cfx = xc - (float)cx;
        int cy0 = min(max(cy,   0), CHW-1), cy1 = min(max(cy+1, 0), CHW-1);
        int cx0 = min(max(cx,   0), CHW-1), cx1 = min(max(cx+1, 0), CHW-1);
#pragma unroll
        for (int c = 0; c < 3; c++) {
            const float* pc = coarse + ((size_t)b * NCc + c) * (CHW * CHW);
            float v00 = pc[cy0*CHW + cx0], v01 = pc[cy0*CHW + cx1];
            float v10 = pc[cy1*CHW + cx0], v11 = pc[cy1*CHW + cx1];
            float top = v00 * (1.f - cfx) + v01 * cfx;
            float bot = v10 * (1.f - cfx) + v11 * cfx;
            g_cflat[(b*NPTS + t)*NCc + c] = top * (1.f - cfy) + bot * cfy;
        }
    }
}

// =========================================================================
// k_smlp: fused fine-gather + 3-layer MLP. 512 threads, 16 rows/block.
// Gather writes DIRECTLY into the row-pair tile xsp via the scramble
// bijection f = p*256+ch -> (r, c) = divmod(f - g0*259, 259); coarse-region
// and pad slots filled from g_cflat / zero. FFMA2 math throughout.
// =========================================================================
__global__ __launch_bounds__(SMLP_THREADS) void k_smlp(const float* __restrict__ fine,
                                                       const float* __restrict__ w3,
                                                       const float* __restrict__ pa,
                                                       float* __restrict__ out) {
    extern __shared__ float sm[];
    float* xsp = sm;                                   // 8 pairs x 260 ch x2
    float* l1p = xsp + NPAIR*FEAT_PAD*2;               // 8 pairs x 260 ch x2
    float* l2s = l1p + NPAIR*FEAT_PAD*2;               // 16 x 128
    __shared__ int   c_b[P_MAX], c_y0[P_MAX], c_y1[P_MAX],
                     c_x0[P_MAX], c_x1[P_MAX], c_fast[P_MAX];
    __shared__ float c_fy[P_MAX], c_fx[P_MAX];

    int tid = threadIdx.x;
    int g0 = blockIdx.x * RPB;
    float a = *pa;

    int f0 = g0 * FEAT_DIM;
    int f1 = (g0 + RPB) * FEAT_DIM - 1;
    int p_lo = 0, np = 0;
    if (f0 < FINE_FLAT) {
        p_lo = f0 >> 8;
        np = (min(f1, FINE_FLAT - 1) >> 8) - p_lo + 1;
    }

    // ---- point coords (fine bilinear: 256->512, src = i/2 - 0.25) ----
    if (tid < np) {
        int p = p_lo + tid;
        int idx = g_pts[p];
        int h = idx >> 9, w = idx & 511;
        float yf = (float)h * 0.5f - 0.25f;
        float xf = (float)w * 0.5f - 0.25f;
        int y0 = (int)floorf(yf); c_fy[tid] = yf - (float)y0;
        int x0 = (int)floorf(xf); c_fx[tid] = xf - (float)x0;
        int sy0 = min(max(y0,   0), FHW-1), sy1 = min(max(y0+1, 0), FHW-1);
        int sx0 = min(max(x0,   0), FHW-1), sx1 = min(max(x0+1, 0), FHW-1);
        c_y0[tid] = sy0; c_y1[tid] = sy1; c_x0[tid] = sx0; c_x1[tid] = sx1;
        c_fast[tid] = (sx1 == sx0 + 1) && ((sx0 & 1) == 0);
        c_b[tid] = p >> 11;
    }
    // ---- coarse-region + pad fill (independent of the coords above) ----
    for (int t = tid; t < RPB*FEAT_PAD; t += SMLP_THREADS) {
        int r = t & 15, c = t >> 4;
        int pi = ((r >> 1) * FEAT_PAD + c) * 2 + (r & 1);
        if (c >= FEAT_DIM) {
            xsp[pi] = 0.f;
        } else {
            int f = (g0 + r) * FEAT_DIM + c;
            if (f >= FINE_FLAT) xsp[pi] = g_cflat[f - FINE_FLAT];
        }
    }
    __syncthreads();

    // ---- fine gather: direct scatter into xsp via the scramble map ----
    {
        int ch = tid & 255;
        for (int i = (tid >> 8); i < np; i += 2) {
            const float* pf = fine + ((size_t)c_b[i] * CF + ch) * (FHW * FHW);
            float v00, v01, v10, v11;
            float sfx = c_fx[i], sfy = c_fy[i];
            if (c_fast[i]) {
                float2 aa = *(const float2*)(pf + c_y0[i]*FHW + c_x0[i]);
                float2 dd = *(const float2*)(pf + c_y1[i]*FHW + c_x0[i]);
                v00 = aa.x; v01 = aa.y; v10 = dd.x; v11 = dd.y;
            } else {
                v00 = pf[c_y0[i]*FHW + c_x0[i]]; v01 = pf[c_y0[i]*FHW + c_x1[i]];
                v10 = pf[c_y1[i]*FHW + c_x0[i]]; v11 = pf[c_y1[i]*FHW + c_x1[i]];
            }
            float top = v00 * (1.f - sfx) + v01 * sfx;
            float bot = v10 * (1.f - sfx) + v11 * sfx;
            float v = top * (1.f - sfy) + bot * sfy;
            int rel = (p_lo + i) * 256 + ch - f0;
            if (rel >= 0 && rel < RPB*FEAT_DIM) {
                int r = rel / FEAT_DIM, c = rel % FEAT_DIM;
                xsp[((r >> 1) * FEAT_PAD + c) * 2 + (r & 1)] = v;
            }
        }
    }
    __syncthreads();

    // ---- tail copy: l1p[c>=256] = xsp[c>=256] (feeds layer 2) ----
    if (tid < NPAIR*8) {
        int pr = tid >> 3, rem = tid & 7;
        int c = 256 + (rem >> 1), lane2 = rem & 1;
        int pi = (pr*FEAT_PAD + c)*2 + lane2;
        l1p[pi] = xsp[pi];
    }

    // ---- layer 1: 259 -> 256, prelu (each half owns 4 row pairs) ----
    {
        int o = tid & 255;
        int half = tid >> 8;
        unsigned long long accp[NPAIR/2];
#pragma unroll
        for (int pp = 0; pp < NPAIR/2; pp++) accp[pp] = 0ull;
        const float4* w1p4 = (const float4*)g_w1p;
        for (int cb = 0; cb < NCB1; cb++) {
            float4 wv = w1p4[cb*256 + o];
            unsigned long long wp0 = pk2(wv.x, wv.x), wp1 = pk2(wv.y, wv.y);
            unsigned long long wp2 = pk2(wv.z, wv.z), wp3 = pk2(wv.w, wv.w);
#pragma unroll
            for (int pp = 0; pp < NPAIR/2; pp++) {
                int pr = half*4 + pp;
                const ulonglong2* xp =
                    (const ulonglong2*)&xsp[(pr*FEAT_PAD + cb*4) * 2];
                ulonglong2 u0 = xp[0], u1 = xp[1];
                fma2(accp[pp], wp0, u0.x);
                fma2(accp[pp], wp1, u0.y);
                fma2(accp[pp], wp2, u1.x);
                fma2(accp[pp], wp3, u1.y);
            }
        }
#pragma unroll
        for (int pp = 0; pp < NPAIR/2; pp++) {
            int pr = half*4 + pp;
            float lo, hi; upk2(accp[pp], lo, hi);
            lo = lo >= 0.f ? lo : a * lo;
            hi = hi >= 0.f ? hi : a * hi;
            ((float2*)l1p)[pr*FEAT_PAD + o] = make_float2(lo, hi);
        }
    }
    __syncthreads();

    // ---- layer 2: 259 -> 128, prelu (each quarter owns 2 row pairs) ----
    {
        int o2 = tid & 127;
        int qtr = tid >> 7;                  // 0..3
        unsigned long long acc2[2];
        acc2[0] = 0ull; acc2[1] = 0ull;
        const float4* w2p4 = (const float4*)g_w2p;
        for (int cb = 0; cb < NCB1; cb++) {
            float4 wv = w2p4[cb*128 + o2];
            unsigned long long wp0 = pk2(wv.x, wv.x), wp1 = pk2(wv.y, wv.y);
            unsigned long long wp2 = pk2(wv.z, wv.z), wp3 = pk2(wv.w, wv.w);
#pragma unroll
            for (int pp = 0; pp < 2; pp++) {
                int pr = qtr*2 + pp;
                const ulonglong2* xp =
                    (const ulonglong2*)&l1p[(pr*FEAT_PAD + cb*4) * 2];
                ulonglong2 u0 = xp[0], u1 = xp[1];
                fma2(acc2[pp], wp0, u0.x);
                fma2(acc2[pp], wp1, u0.y);
                fma2(acc2[pp], wp2, u1.x);
                fma2(acc2[pp], wp3, u1.y);
            }
        }
#pragma unroll
        for (int pp = 0; pp < 2; pp++) {
            int pr = qtr*2 + pp;
            float lo, hi; upk2(acc2[pp], lo, hi);
            lo = lo >= 0.f ? lo : a * lo;
            hi = hi >= 0.f ? hi : a * hi;
            l2s[(2*pr  )*128 + o2] = lo;
            l2s[(2*pr+1)*128 + o2] = hi;
        }
    }
    __syncthreads();

    // ---- layer 3: 131 -> 3 ----
    if (tid < RPB*NCc) {
        int r = tid / 3, oo = tid % 3;
        float s = 0.f;
        for (int c = 0; c < 128; c++) s = fmaf(w3[oo*131 + c], l2s[r*128 + c], s);
#pragma unroll
        for (int t = 0; t < 3; t++) {
            float xt = xsp[((r >> 1)*FEAT_PAD + 256 + t)*2 + (r & 1)];
            s = fmaf(w3[oo*131 + 128 + t], xt, s);
        }
        int g = g0 + r;
        int b = g >> 11, n = g & 2047;
        out[(b*NCc + oo)*NPTS + n] = s;
    }
}

// ---------------- launch ----------------
extern "C" void kernel_launch(void* const* d_in, const int* in_sizes, int n_in,
                              void* d_out, int out_size) {
    const float* fine   = (const float*)d_in[0];
    const float* coarse = (const float*)d_in[1];
    const float* w1     = (const float*)d_in[2];
    const float* w2     = (const float*)d_in[3];
    const float* w3     = (const float*)d_in[4];
    const float* pa     = (const float*)d_in[5];
    const int*   rnd    = (const int*)d_in[6];
    float* out = (float*)d_out;

    static int configured = 0;
    int smlp_smem = (2*NPAIR*FEAT_PAD*2 + RPB*128) * (int)sizeof(float);
    if (!configured) {
        cudaFuncSetAttribute(k_prep, cudaFuncAttributeMaxDynamicSharedMemorySize,
                             NWORDS * (int)sizeof(unsigned int));
        cudaFuncSetAttribute(k_smlp, cudaFuncAttributeMaxDynamicSharedMemorySize,
                             smlp_smem);
        configured = 1;
    }

    cudaMemsetAsync(out + OUT_OFF, 0, (size_t)MASK_SIZE * sizeof(float), 0);
    k_prep<<<PREP_SEL_BLOCKS + PREP_REPACK_BLOCKS, 1024,
             NWORDS * sizeof(unsigned int)>>>(coarse, rnd, w1, w2, out + OUT_OFF);
    k_smlp<<<NROWS/RPB, SMLP_THREADS, smlp_smem>>>(fine, w3, pa, out);
    (void)in_sizes; (void)n_in; (void)out_size;
}